// round 4
// baseline (speedup 1.0000x reference)
#include <cuda_runtime.h>
#include <cuda_fp16.h>
#include <cstdint>
#include <cstddef>

#define LSEQ 512
#define NBATCH 512
#define IDIM 128
#define HDIM 128
#define GDIM 512   // 4*H

// Scratch: packed fp16 pre-activation input gates.
// Layout: [m = t*N+n][hcol 0..127][gate 0..3]  -> 8 bytes per (m, hcol)
__device__ __half g_XgH[(size_t)LSEQ * NBATCH * GDIM];

// ---------------------------------------------------------------------------
// helpers
// ---------------------------------------------------------------------------
__device__ __forceinline__ uint32_t f2h2(float a, float b) {
    __half2 h = __floats2half2_rn(a, b);
    return *reinterpret_cast<uint32_t*>(&h);
}

__device__ __forceinline__ void mma16816(float* d,
    uint32_t a0, uint32_t a1, uint32_t a2, uint32_t a3,
    uint32_t b0, uint32_t b1)
{
    asm volatile(
        "mma.sync.aligned.m16n8k16.row.col.f32.f16.f16.f32 "
        "{%0,%1,%2,%3}, {%4,%5,%6,%7}, {%8,%9}, {%0,%1,%2,%3};\n"
        : "+f"(d[0]), "+f"(d[1]), "+f"(d[2]), "+f"(d[3])
        : "r"(a0), "r"(a1), "r"(a2), "r"(a3), "r"(b0), "r"(b1));
}

__device__ __forceinline__ void ldsm4(uint32_t& a0, uint32_t& a1,
                                      uint32_t& a2, uint32_t& a3, uint32_t saddr)
{
    asm volatile("ldmatrix.sync.aligned.m8n8.x4.shared.b16 {%0,%1,%2,%3}, [%4];"
                 : "=r"(a0), "=r"(a1), "=r"(a2), "=r"(a3) : "r"(saddr));
}

__device__ __forceinline__ float ex2f(float x) {
    float y; asm("ex2.approx.f32 %0, %1;" : "=f"(y) : "f"(x)); return y;
}
__device__ __forceinline__ float rcpf(float x) {
    float y; asm("rcp.approx.f32 %0, %1;" : "=f"(y) : "f"(x)); return y;
}
// accurate sigmoid/tanh (EX2 ~2ulp, RCP ~1ulp) — NOT tanh.approx
__device__ __forceinline__ float sigf(float x) {
    return rcpf(1.0f + ex2f(-1.44269504f * x));
}
__device__ __forceinline__ float tanh_fast(float x) {
    return __fmaf_rn(2.0f, sigf(2.0f * x), -1.0f);
}

// ---------------------------------------------------------------------------
// Phase 1: Xg = x@W_ih^T + (b_ih+b_hh), packed fp16 [m][hcol][gate].
// Grid 1024 x 512 threads. 256 M-rows/block, 8 subtiles of 32, double-buffered
// A smem with register prefetch. Warp w owns hcols [8w,8w+8) for all 4 gates.
// ---------------------------------------------------------------------------
__global__ void __launch_bounds__(512, 1)
pregemm_kernel(const float* __restrict__ x,
               const float* __restrict__ Wih,
               const float* __restrict__ bih,
               const float* __restrict__ bhh)
{
    __shared__ __half Ash[2][32][136];   // 272B pitch, conflict-free

    const int tid  = threadIdx.x;
    const int warp = tid >> 5;
    const int lane = tid & 31;
    const int q    = lane & 3;
    const int r0   = lane >> 2;
    const int c0   = warp * 8 + q * 2;   // hcol pair base (per-gate col)

    // --- B fragments: W_ih rows for gate tiles j at cols j*128 + [8w,8w+8) ---
    uint32_t bfrag[4][8][2];
#pragma unroll
    for (int j = 0; j < 4; j++) {
        const float* wr = Wih + (size_t)(j * 128 + warp * 8 + r0) * IDIM;
#pragma unroll
        for (int kt = 0; kt < 8; kt++) {
            const int k = kt * 16 + q * 2;
            float2 w0 = *reinterpret_cast<const float2*>(wr + k);
            float2 w1 = *reinterpret_cast<const float2*>(wr + k + 8);
            bfrag[j][kt][0] = f2h2(w0.x, w0.y);
            bfrag[j][kt][1] = f2h2(w1.x, w1.y);
        }
    }

    // --- bias per gate for cols c0, c0+1 ---
    float bx[4], by[4];
#pragma unroll
    for (int j = 0; j < 4; j++) {
        bx[j] = bih[j * 128 + c0]     + bhh[j * 128 + c0];
        by[j] = bih[j * 128 + c0 + 1] + bhh[j * 128 + c0 + 1];
    }

    const int lr = tid >> 4;           // 0..31
    const int lc = (tid & 15) * 8;     // 0..120
    const size_t m_base = (size_t)blockIdx.x * 256;

    const int lm_row = lane & 15;
    const int lm_col = (lane >> 4) * 8;

    // prefetch subtile 0
    float4 v0 = *reinterpret_cast<const float4*>(x + (m_base + lr) * IDIM + lc);
    float4 v1 = *reinterpret_cast<const float4*>(x + (m_base + lr) * IDIM + lc + 4);

#pragma unroll 1
    for (int s = 0; s < 8; s++) {
        const int buf = s & 1;
        {
            __half2* sp = reinterpret_cast<__half2*>(&Ash[buf][lr][lc]);
            sp[0] = __floats2half2_rn(v0.x, v0.y);
            sp[1] = __floats2half2_rn(v0.z, v0.w);
            sp[2] = __floats2half2_rn(v1.x, v1.y);
            sp[3] = __floats2half2_rn(v1.z, v1.w);
        }
        __syncthreads();

        if (s < 7) {
            const size_t mr = m_base + (s + 1) * 32 + lr;
            v0 = *reinterpret_cast<const float4*>(x + mr * IDIM + lc);
            v1 = *reinterpret_cast<const float4*>(x + mr * IDIM + lc + 4);
        }

        float acc[2][4][4];
#pragma unroll
        for (int mi = 0; mi < 2; mi++)
#pragma unroll
            for (int j = 0; j < 4; j++)
#pragma unroll
                for (int p = 0; p < 4; p++) acc[mi][j][p] = 0.0f;

#pragma unroll
        for (int kt = 0; kt < 8; kt++) {
#pragma unroll
            for (int mi = 0; mi < 2; mi++) {
                uint32_t a0, a1, a2, a3;
                uint32_t saddr = (uint32_t)__cvta_generic_to_shared(
                    &Ash[buf][mi * 16 + lm_row][kt * 16 + lm_col]);
                ldsm4(a0, a1, a2, a3, saddr);
#pragma unroll
                for (int j = 0; j < 4; j++)
                    mma16816(acc[mi][j], a0, a1, a2, a3, bfrag[j][kt][0], bfrag[j][kt][1]);
            }
        }

        const size_t m0 = m_base + s * 32;
#pragma unroll
        for (int mi = 0; mi < 2; mi++) {
#pragma unroll
            for (int half_ = 0; half_ < 2; half_++) {
                const size_t row = m0 + mi * 16 + r0 + half_ * 8;
                const int pa = half_ * 2;
                uint4 v;
                v.x = f2h2(acc[mi][0][pa]     + bx[0], acc[mi][1][pa]     + bx[1]);
                v.y = f2h2(acc[mi][2][pa]     + bx[2], acc[mi][3][pa]     + bx[3]);
                v.z = f2h2(acc[mi][0][pa + 1] + by[0], acc[mi][1][pa + 1] + by[1]);
                v.w = f2h2(acc[mi][2][pa + 1] + by[2], acc[mi][3][pa + 1] + by[3]);
                *reinterpret_cast<uint4*>(&g_XgH[(row * 128 + c0) * 4]) = v;
            }
        }
    }
}

// ---------------------------------------------------------------------------
// Phase 2: masked LSTM recurrence.
// Grid 128 blocks x 4 batch rows, 512 threads (16 warps). Warp w owns hcols
// [8w,8w+8) for all four gates; shuffle-redistributed 1-element/lane epilogue.
// Only 4 batch rows are valid -> rows 8-15 of the m16 A-tile are structurally
// zero: load ONLY top-half matrices (4 ldsm.x4/warp/step packing kt & kt+1),
// pass constant-zero regs for a1/a3. Halves smem-crossbar traffic vs R3.
// ---------------------------------------------------------------------------
__global__ void __launch_bounds__(512, 1)
lstm_rec_kernel(const float* __restrict__ hc,
                const int*   __restrict__ is_init,
                const float* __restrict__ Whh,
                float* __restrict__ out)
{
    __shared__ __half hbuf[2][8][136];    // double-buffered h (rows 4..7 zero)
    __shared__ float  msk[LSEQ][4];       // 8KB mask table

    const int tid  = threadIdx.x;
    const int warp = tid >> 5;
    const int lane = tid & 31;
    const int q    = lane & 3;
    const int r0   = lane >> 2;
    const int n0   = blockIdx.x * 4;

    // element ownership (post-shuffle): one element per lane
    const int er   = lane >> 3;                 // batch row 0..3
    const int ec   = lane & 7;                  // col idx in warp
    const int col  = warp * 8 + ec;             // global hcol
    const int n    = n0 + er;
    const int srcLane = er * 4 + (ec >> 1);     // lane holding this element's frags
    const int par  = ec & 1;

    // --- W_hh B-fragments: gate tile j covers cols j*128 + [8w,8w+8) ---
    uint32_t bfrag[4][8][2];
#pragma unroll
    for (int j = 0; j < 4; j++) {
        const float* wr = Whh + (size_t)(j * 128 + warp * 8 + r0) * HDIM;
#pragma unroll
        for (int kt = 0; kt < 8; kt++) {
            const int k = kt * 16 + q * 2;
            float2 w0 = *reinterpret_cast<const float2*>(wr + k);
            float2 w1 = *reinterpret_cast<const float2*>(wr + k + 8);
            bfrag[j][kt][0] = f2h2(w0.x, w0.y);
            bfrag[j][kt][1] = f2h2(w1.x, w1.y);
        }
    }

    // --- mask table + zero rows 4..7 of both h buffers ---
    for (int idx = tid; idx < LSEQ * 4; idx += 512) {
        const int t = idx >> 2, r = idx & 3;
        msk[t][r] = 1.0f - (float)is_init[(size_t)t * NBATCH + n0 + r];
    }
    for (int idx = tid; idx < 2 * 4 * 136; idx += 512) {
        const int b = idx / (4 * 136), rem = idx % (4 * 136);
        hbuf[b][4 + rem / 136][rem % 136] = __half(0);
    }
    __syncthreads();

    // --- init state (t=0 mask applied); each lane owns one element ---
    const float m0v = msk[0][er];
    float creg = hc[(size_t)n * 256 + 128 + col] * m0v;
    hbuf[0][er][col] = __float2half(hc[(size_t)n * 256 + col] * m0v);
    __syncthreads();

    // per-lane Xg pointer: 8B per (m, hcol)
    const uint2* xgp = reinterpret_cast<const uint2*>(g_XgH);
    uint2 xcur = __ldg(&xgp[(size_t)n * 128 + col]);     // t = 0

    // ldmatrix lane base: group g = lane>>3 -> row lane&7, col g*8
    // (g0: kt lo | g1: kt hi | g2: kt+1 lo | g3: kt+1 hi); pair p at +64B
    const int lmr = lane & 7;
    const int lmc = (lane >> 3) * 8;
    const uint32_t lmBase0 = (uint32_t)__cvta_generic_to_shared(&hbuf[0][lmr][lmc]);
    const uint32_t lmBase1 = (uint32_t)__cvta_generic_to_shared(&hbuf[1][lmr][lmc]);

    const uint32_t ZED = 0u;
    const size_t OUT_HC = (size_t)LSEQ * NBATCH * HDIM;

#pragma unroll 1
    for (int t = 0; t < LSEQ; t++) {
        // prefetch next step's Xg
        const int tn = (t < LSEQ - 1) ? t + 1 : t;
        uint2 xnext = __ldg(&xgp[((size_t)tn * NBATCH + n) * 128 + col]);

        // --- MMA: 4 gate tiles x 8 kt, top-half A only ---
        float acc[4][4];
#pragma unroll
        for (int j = 0; j < 4; j++)
#pragma unroll
            for (int p = 0; p < 4; p++) acc[j][p] = 0.0f;

        const uint32_t lb = (t & 1) ? lmBase1 : lmBase0;
#pragma unroll
        for (int p = 0; p < 4; p++) {
            uint32_t r0a, r1a, r2a, r3a;          // a0(kt), a2(kt), a0(kt+1), a2(kt+1)
            ldsm4(r0a, r1a, r2a, r3a, lb + p * 64);
#pragma unroll
            for (int j = 0; j < 4; j++)
                mma16816(acc[j], r0a, ZED, r1a, ZED, bfrag[j][2 * p][0], bfrag[j][2 * p][1]);
#pragma unroll
            for (int j = 0; j < 4; j++)
                mma16816(acc[j], r2a, ZED, r3a, ZED, bfrag[j][2 * p + 1][0], bfrag[j][2 * p + 1][1]);
        }

        // --- shuffle-redistribute: 1 element per lane ---
        float g[4];
#pragma unroll
        for (int j = 0; j < 4; j++) {
            const float v0 = __shfl_sync(0xffffffffu, acc[j][0], srcLane);
            const float v1 = __shfl_sync(0xffffffffu, acc[j][1], srcLane);
            g[j] = par ? v1 : v0;
        }

        // --- epilogue (gate order i,f,g,o) ---
        const float2 x01 = __half22float2(*reinterpret_cast<__half2*>(&xcur.x));
        const float2 x23 = __half22float2(*reinterpret_cast<__half2*>(&xcur.y));

        const float i_ = sigf(g[0] + x01.x);
        const float f_ = sigf(g[1] + x01.y);
        const float g_ = tanh_fast(g[2] + x23.x);
        const float o_ = sigf(g[3] + x23.y);
        const float cn = __fmaf_rn(f_, creg, i_ * g_);
        const float hv = o_ * tanh_fast(cn);

        out[((size_t)t * NBATCH + n) * HDIM + col] = hv;

        const float mn = (t < LSEQ - 1) ? msk[t + 1][er] : 1.0f;
        creg = cn * mn;
        hbuf[(t + 1) & 1][er][col] = __float2half(hv * mn);

        if (t == LSEQ - 1) {
            out[OUT_HC + (size_t)n * 256 + col]       = hv;
            out[OUT_HC + (size_t)n * 256 + 128 + col] = cn;
        }
        __syncthreads();
        xcur = xnext;
    }
}

// ---------------------------------------------------------------------------
extern "C" void kernel_launch(void* const* d_in, const int* in_sizes, int n_in,
                              void* d_out, int out_size)
{
    const float* input   = (const float*)d_in[0];  // [L,N,I] fp32
    const float* hc      = (const float*)d_in[1];  // [N,2H]  fp32
    const int*   is_init = (const int*)  d_in[2];  // [L,N]   int32
    const float* Wih     = (const float*)d_in[3];  // [4H,I]
    const float* Whh     = (const float*)d_in[4];  // [4H,H]
    const float* bih     = (const float*)d_in[5];  // [4H]
    const float* bhh     = (const float*)d_in[6];  // [4H]
    float* out = (float*)d_out;                    // [L,N,H] then [N,2H]

    pregemm_kernel<<<(LSEQ * NBATCH) / 256, 512>>>(input, Wih, bih, bhh);
    lstm_rec_kernel<<<NBATCH / 4, 512>>>(hc, is_init, Whh, out);
}

// round 5
// speedup vs baseline: 1.4078x; 1.4078x over previous
#include <cuda_runtime.h>
#include <cuda_fp16.h>
#include <cstdint>
#include <cstddef>

#define LSEQ 512
#define NBATCH 512
#define IDIM 128
#define HDIM 128
#define GDIM 512   // 4*H

// Scratch: packed fp16 pre-activation input gates.
// Layout: [m = t*N+n][hcol 0..127][gate 0..3]  -> 8 bytes per (m, hcol)
__device__ __half g_XgH[(size_t)LSEQ * NBATCH * GDIM];

// ---------------------------------------------------------------------------
// helpers
// ---------------------------------------------------------------------------
__device__ __forceinline__ uint32_t f2h2(float a, float b) {
    __half2 h = __floats2half2_rn(a, b);
    return *reinterpret_cast<uint32_t*>(&h);
}

__device__ __forceinline__ void mma16816(float* d,
    uint32_t a0, uint32_t a1, uint32_t a2, uint32_t a3,
    uint32_t b0, uint32_t b1)
{
    asm volatile(
        "mma.sync.aligned.m16n8k16.row.col.f32.f16.f16.f32 "
        "{%0,%1,%2,%3}, {%4,%5,%6,%7}, {%8,%9}, {%0,%1,%2,%3};\n"
        : "+f"(d[0]), "+f"(d[1]), "+f"(d[2]), "+f"(d[3])
        : "r"(a0), "r"(a1), "r"(a2), "r"(a3), "r"(b0), "r"(b1));
}

__device__ __forceinline__ void ldsm4(uint32_t& a0, uint32_t& a1,
                                      uint32_t& a2, uint32_t& a3, uint32_t saddr)
{
    asm volatile("ldmatrix.sync.aligned.m8n8.x4.shared.b16 {%0,%1,%2,%3}, [%4];"
                 : "=r"(a0), "=r"(a1), "=r"(a2), "=r"(a3) : "r"(saddr));
}

__device__ __forceinline__ float ex2f(float x) {
    float y; asm("ex2.approx.f32 %0, %1;" : "=f"(y) : "f"(x)); return y;
}
__device__ __forceinline__ float rcpf(float x) {
    float y; asm("rcp.approx.f32 %0, %1;" : "=f"(y) : "f"(x)); return y;
}
// accurate sigmoid/tanh (EX2 ~2ulp, RCP ~1ulp) — NOT tanh.approx
__device__ __forceinline__ float sigf(float x) {
    return rcpf(1.0f + ex2f(-1.44269504f * x));
}
__device__ __forceinline__ float tanh_fast(float x) {
    return __fmaf_rn(2.0f, sigf(2.0f * x), -1.0f);
}

// ---------------------------------------------------------------------------
// Phase 1: Xg = x@W_ih^T + (b_ih+b_hh), packed fp16 [m][hcol][gate].
// Grid 1024 x 512 threads. 256 M-rows/block, 8 subtiles of 32, double-buffered
// A smem with register prefetch. Warp w owns hcols [8w,8w+8) for all 4 gates.
// ---------------------------------------------------------------------------
__global__ void __launch_bounds__(512, 1)
pregemm_kernel(const float* __restrict__ x,
               const float* __restrict__ Wih,
               const float* __restrict__ bih,
               const float* __restrict__ bhh)
{
    __shared__ __half Ash[2][32][136];   // 272B pitch, conflict-free

    const int tid  = threadIdx.x;
    const int warp = tid >> 5;
    const int lane = tid & 31;
    const int q    = lane & 3;
    const int r0   = lane >> 2;
    const int c0   = warp * 8 + q * 2;   // hcol pair base (per-gate col)

    // --- B fragments: W_ih rows for gate tiles j at cols j*128 + [8w,8w+8) ---
    uint32_t bfrag[4][8][2];
#pragma unroll
    for (int j = 0; j < 4; j++) {
        const float* wr = Wih + (size_t)(j * 128 + warp * 8 + r0) * IDIM;
#pragma unroll
        for (int kt = 0; kt < 8; kt++) {
            const int k = kt * 16 + q * 2;
            float2 w0 = *reinterpret_cast<const float2*>(wr + k);
            float2 w1 = *reinterpret_cast<const float2*>(wr + k + 8);
            bfrag[j][kt][0] = f2h2(w0.x, w0.y);
            bfrag[j][kt][1] = f2h2(w1.x, w1.y);
        }
    }

    // --- bias per gate for cols c0, c0+1 ---
    float bx[4], by[4];
#pragma unroll
    for (int j = 0; j < 4; j++) {
        bx[j] = bih[j * 128 + c0]     + bhh[j * 128 + c0];
        by[j] = bih[j * 128 + c0 + 1] + bhh[j * 128 + c0 + 1];
    }

    const int lr = tid >> 4;           // 0..31
    const int lc = (tid & 15) * 8;     // 0..120
    const size_t m_base = (size_t)blockIdx.x * 256;

    const int lm_row = lane & 15;
    const int lm_col = (lane >> 4) * 8;

    // prefetch subtile 0
    float4 v0 = *reinterpret_cast<const float4*>(x + (m_base + lr) * IDIM + lc);
    float4 v1 = *reinterpret_cast<const float4*>(x + (m_base + lr) * IDIM + lc + 4);

#pragma unroll 1
    for (int s = 0; s < 8; s++) {
        const int buf = s & 1;
        {
            __half2* sp = reinterpret_cast<__half2*>(&Ash[buf][lr][lc]);
            sp[0] = __floats2half2_rn(v0.x, v0.y);
            sp[1] = __floats2half2_rn(v0.z, v0.w);
            sp[2] = __floats2half2_rn(v1.x, v1.y);
            sp[3] = __floats2half2_rn(v1.z, v1.w);
        }
        __syncthreads();

        if (s < 7) {
            const size_t mr = m_base + (s + 1) * 32 + lr;
            v0 = *reinterpret_cast<const float4*>(x + mr * IDIM + lc);
            v1 = *reinterpret_cast<const float4*>(x + mr * IDIM + lc + 4);
        }

        float acc[2][4][4];
#pragma unroll
        for (int mi = 0; mi < 2; mi++)
#pragma unroll
            for (int j = 0; j < 4; j++)
#pragma unroll
                for (int p = 0; p < 4; p++) acc[mi][j][p] = 0.0f;

#pragma unroll
        for (int kt = 0; kt < 8; kt++) {
#pragma unroll
            for (int mi = 0; mi < 2; mi++) {
                uint32_t a0, a1, a2, a3;
                uint32_t saddr = (uint32_t)__cvta_generic_to_shared(
                    &Ash[buf][mi * 16 + lm_row][kt * 16 + lm_col]);
                ldsm4(a0, a1, a2, a3, saddr);
#pragma unroll
                for (int j = 0; j < 4; j++)
                    mma16816(acc[mi][j], a0, a1, a2, a3, bfrag[j][kt][0], bfrag[j][kt][1]);
            }
        }

        const size_t m0 = m_base + s * 32;
#pragma unroll
        for (int mi = 0; mi < 2; mi++) {
#pragma unroll
            for (int half_ = 0; half_ < 2; half_++) {
                const size_t row = m0 + mi * 16 + r0 + half_ * 8;
                const int pa = half_ * 2;
                uint4 v;
                v.x = f2h2(acc[mi][0][pa]     + bx[0], acc[mi][1][pa]     + bx[1]);
                v.y = f2h2(acc[mi][2][pa]     + bx[2], acc[mi][3][pa]     + bx[3]);
                v.z = f2h2(acc[mi][0][pa + 1] + by[0], acc[mi][1][pa + 1] + by[1]);
                v.w = f2h2(acc[mi][2][pa + 1] + by[2], acc[mi][3][pa + 1] + by[3]);
                *reinterpret_cast<uint4*>(&g_XgH[(row * 128 + c0) * 4]) = v;
            }
        }
    }
}

// ---------------------------------------------------------------------------
// Phase 2: masked LSTM recurrence — TRANSPOSED GEMM (W-stationary).
// gates^T[512,4] = W_hh[512,128] @ h^T[128,4].  M = gates, N = batch, K = h.
// Grid 128 blocks x 4 batch rows, 512 threads (16 warps).
// Warp w owns gate rows [32w, 32w+32) = 2 m16 tiles; A-frags (W_hh) loaded
// once (64 regs). B-frags (h) via 4 plain ldmatrix.x4 per step from hbuf
// [n][k] (trans-of-trans cancels). 16 MMAs/warp/step (half of R4).
// Gate pre-acts cross warps through an 8KB smem buffer gsh[gate][n];
// epilogue is 1 element/lane. Two barriers per step.
// ---------------------------------------------------------------------------
__global__ void __launch_bounds__(512, 1)
lstm_rec_kernel(const float* __restrict__ hc,
                const int*   __restrict__ is_init,
                const float* __restrict__ Whh,
                float* __restrict__ out)
{
    __shared__ __half hbuf[2][8][136];    // h state [n][k], rows 4..7 zero
    __shared__ float  gsh[GDIM][4];       // gate preacts [gate][n], 8KB
    __shared__ float  msk[LSEQ][4];       // 8KB mask table

    const int tid  = threadIdx.x;
    const int warp = tid >> 5;
    const int lane = tid & 31;
    const int q    = lane & 3;
    const int r0   = lane >> 2;
    const int n0   = blockIdx.x * 4;

    // epilogue element ownership: 1 element per lane
    const int er   = lane >> 3;                 // batch row 0..3
    const int ec   = lane & 7;                  // col idx in warp
    const int col  = warp * 8 + ec;             // global hcol
    const int n    = n0 + er;

    // --- A-fragments: W_hh gate rows [32w, 32w+32), loaded once ---
    // afrag[mt][kt][0..3]: a0=[r][c], a1=[r+8][c], a2=[r][c+8], a3=[r+8][c+8]
    uint32_t afrag[2][8][4];
#pragma unroll
    for (int mt = 0; mt < 2; mt++) {
        const int grow = warp * 32 + mt * 16 + r0;
#pragma unroll
        for (int kt = 0; kt < 8; kt++) {
            const int k = kt * 16 + q * 2;
            float2 w00 = *reinterpret_cast<const float2*>(Whh + (size_t)grow * HDIM + k);
            float2 w01 = *reinterpret_cast<const float2*>(Whh + (size_t)grow * HDIM + k + 8);
            float2 w10 = *reinterpret_cast<const float2*>(Whh + (size_t)(grow + 8) * HDIM + k);
            float2 w11 = *reinterpret_cast<const float2*>(Whh + (size_t)(grow + 8) * HDIM + k + 8);
            afrag[mt][kt][0] = f2h2(w00.x, w00.y);
            afrag[mt][kt][1] = f2h2(w10.x, w10.y);
            afrag[mt][kt][2] = f2h2(w01.x, w01.y);
            afrag[mt][kt][3] = f2h2(w11.x, w11.y);
        }
    }

    // --- mask table + zero rows 4..7 of both h buffers ---
    for (int idx = tid; idx < LSEQ * 4; idx += 512) {
        const int t = idx >> 2, r = idx & 3;
        msk[t][r] = 1.0f - (float)is_init[(size_t)t * NBATCH + n0 + r];
    }
    for (int idx = tid; idx < 2 * 4 * 136; idx += 512) {
        const int b = idx / (4 * 136), rem = idx % (4 * 136);
        hbuf[b][4 + rem / 136][rem % 136] = __half(0);
    }
    __syncthreads();

    // --- init state (t=0 mask applied); each lane owns one element ---
    const float m0v = msk[0][er];
    float creg = hc[(size_t)n * 256 + 128 + col] * m0v;
    hbuf[0][er][col] = __float2half(hc[(size_t)n * 256 + col] * m0v);
    __syncthreads();

    // per-lane Xg pointer: 8B per (m, hcol)
    const uint2* xgp = reinterpret_cast<const uint2*>(g_XgH);
    uint2 xcur = __ldg(&xgp[(size_t)n * 128 + col]);     // t = 0

    // ldmatrix lane base for B-frags: matrix g = lane>>3 at k-col g*8,
    // row = lane&7; step p advances k by 32 (64 bytes).
    const int lmr = lane & 7;
    const int lmg = (lane >> 3) * 8;
    const uint32_t lmBase0 = (uint32_t)__cvta_generic_to_shared(&hbuf[0][lmr][lmg]);
    const uint32_t lmBase1 = (uint32_t)__cvta_generic_to_shared(&hbuf[1][lmr][lmg]);

    // gate STS: lanes with q<2 hold valid cols n = 2q, 2q+1
    const bool wlane = (q < 2);
    const int gbase = warp * 32 + r0;           // + mt*16 + u*8

    const size_t OUT_HC = (size_t)LSEQ * NBATCH * HDIM;

#pragma unroll 1
    for (int t = 0; t < LSEQ; t++) {
        // prefetch next step's Xg
        const int tn = (t < LSEQ - 1) ? t + 1 : t;
        uint2 xnext = __ldg(&xgp[((size_t)tn * NBATCH + n) * 128 + col]);

        // --- MMA: gates^T = W_hh @ h^T, 2 m-tiles x 8 kt ---
        float acc[2][4];
#pragma unroll
        for (int mt = 0; mt < 2; mt++)
#pragma unroll
            for (int p = 0; p < 4; p++) acc[mt][p] = 0.0f;

        const uint32_t lb = (t & 1) ? lmBase1 : lmBase0;
#pragma unroll
        for (int p = 0; p < 4; p++) {
            uint32_t b0, b1, b2, b3;   // b0(2p), b1(2p), b0(2p+1), b1(2p+1)
            ldsm4(b0, b1, b2, b3, lb + p * 64);
#pragma unroll
            for (int mt = 0; mt < 2; mt++) {
                mma16816(acc[mt], afrag[mt][2*p][0],   afrag[mt][2*p][1],
                                  afrag[mt][2*p][2],   afrag[mt][2*p][3],   b0, b1);
                mma16816(acc[mt], afrag[mt][2*p+1][0], afrag[mt][2*p+1][1],
                                  afrag[mt][2*p+1][2], afrag[mt][2*p+1][3], b2, b3);
            }
        }

        // --- stage gate pre-acts: gsh[gate][n] (valid n = 2q, 2q+1 for q<2) ---
        if (wlane) {
#pragma unroll
            for (int mt = 0; mt < 2; mt++) {
                *reinterpret_cast<float2*>(&gsh[gbase + mt * 16][2 * q]) =
                    make_float2(acc[mt][0], acc[mt][1]);
                *reinterpret_cast<float2*>(&gsh[gbase + mt * 16 + 8][2 * q]) =
                    make_float2(acc[mt][2], acc[mt][3]);
            }
        }
        __syncthreads();   // bar1: gates visible

        // --- epilogue: 1 element (er, col) per lane; gate order i,f,g,o ---
        const float2 x01 = __half22float2(*reinterpret_cast<__half2*>(&xcur.x));
        const float2 x23 = __half22float2(*reinterpret_cast<__half2*>(&xcur.y));

        const float i_ = sigf(gsh[col][er]        + x01.x);
        const float f_ = sigf(gsh[128 + col][er]  + x01.y);
        const float g_ = tanh_fast(gsh[256 + col][er] + x23.x);
        const float o_ = sigf(gsh[384 + col][er]  + x23.y);
        const float cn = __fmaf_rn(f_, creg, i_ * g_);
        const float hv = o_ * tanh_fast(cn);

        out[((size_t)t * NBATCH + n) * HDIM + col] = hv;

        const float mn = (t < LSEQ - 1) ? msk[t + 1][er] : 1.0f;
        creg = cn * mn;
        hbuf[(t + 1) & 1][er][col] = __float2half(hv * mn);

        if (t == LSEQ - 1) {
            out[OUT_HC + (size_t)n * 256 + col]       = hv;
            out[OUT_HC + (size_t)n * 256 + 128 + col] = cn;
        }
        __syncthreads();   // bar2: h(t+1) visible, gsh free for reuse
        xcur = xnext;
    }
}

// ---------------------------------------------------------------------------
extern "C" void kernel_launch(void* const* d_in, const int* in_sizes, int n_in,
                              void* d_out, int out_size)
{
    const float* input   = (const float*)d_in[0];  // [L,N,I] fp32
    const float* hc      = (const float*)d_in[1];  // [N,2H]  fp32
    const int*   is_init = (const int*)  d_in[2];  // [L,N]   int32
    const float* Wih     = (const float*)d_in[3];  // [4H,I]
    const float* Whh     = (const float*)d_in[4];  // [4H,H]
    const float* bih     = (const float*)d_in[5];  // [4H]
    const float* bhh     = (const float*)d_in[6];  // [4H]
    float* out = (float*)d_out;                    // [L,N,H] then [N,2H]

    pregemm_kernel<<<(LSEQ * NBATCH) / 256, 512>>>(input, Wih, bih, bhh);
    lstm_rec_kernel<<<NBATCH / 4, 512>>>(hc, is_init, Whh, out);
}